// round 7
// baseline (speedup 1.0000x reference)
#include <cuda_runtime.h>
#include <cstdint>
#include <math.h>

// ---------------- problem constants ----------------
#define BATCH 8192
#define IN_F  1024
#define OUT_F 1024
#define NB    8
#define KTOT  9216                       // 1024 (silu) + 8192 (basis)

// ---------------- GEMM tiling ----------------
#define BM 128
#define BN 256
#define BK 32                            // 32 tf32 = 128 bytes = one SW128 row
#define STAGES 4
#define NITER (KTOT / BK)                // 288
#define STAGE_BYTES ((BM + BN) * 128)    // 49152
#define BB_OFF (BM * 128)                // 16384
#define SMEM_DYN (STAGES * STAGE_BYTES)  // 196608

// scratch (allocation-free rule: __device__ globals)
__device__ float g_A[(size_t)BATCH * KTOT];   // 302 MB
__device__ float g_W[(size_t)OUT_F * KTOT];   //  38 MB

// ---------------- helpers ----------------
__device__ __forceinline__ uint32_t smem_u32(const void* p) {
    uint32_t a;
    asm("{ .reg .u64 t; cvta.to.shared.u64 t, %1; cvt.u32.u64 %0, t; }" : "=r"(a) : "l"(p));
    return a;
}
__device__ __forceinline__ float tf32_rna(float x) {          // sm_80+ legal
    uint32_t r;
    asm("cvt.rna.tf32.f32 %0, %1;" : "=r"(r) : "f"(x));
    return __uint_as_float(r);
}

#define SWZ(o) ((o) ^ (((o) >> 3) & 0x70))

__device__ __forceinline__ void cp16(uint32_t dst, const void* src) {
    asm volatile("cp.async.cg.shared.global [%0], [%1], 16;"
                 :: "r"(dst), "l"(__cvta_generic_to_global(src)));
}
#define CP_COMMIT() asm volatile("cp.async.commit_group;" ::: "memory")
#define CP_WAIT_2() asm volatile("cp.async.wait_group 2;" ::: "memory")

#define LDSM4(r, addr) \
    asm volatile("ldmatrix.sync.aligned.m8n8.x4.shared.b16 {%0,%1,%2,%3}, [%4];" \
        : "=r"((r)[0]), "=r"((r)[1]), "=r"((r)[2]), "=r"((r)[3]) : "r"(addr))

// m16n8k8 tf32 MMA (sm_80+ baseline feature — legal on plain sm_103 target)
__device__ __forceinline__ void mma_tf32(float* c, const uint32_t* a,
                                         uint32_t b0, uint32_t b1) {
    asm volatile(
        "mma.sync.aligned.m16n8k8.row.col.f32.tf32.tf32.f32 "
        "{%0,%1,%2,%3}, {%4,%5,%6,%7}, {%8,%9}, {%0,%1,%2,%3};"
        : "+f"(c[0]), "+f"(c[1]), "+f"(c[2]), "+f"(c[3])
        : "r"(a[0]), "r"(a[1]), "r"(a[2]), "r"(a[3]), "r"(b0), "r"(b1));
}

// =====================================================================
// P0: A = [ tf32(silu(x)) | tf32(bspline_basis(clip(x))) ]  (B, 9216)
// =====================================================================
__global__ void prep_A_kernel(const float* __restrict__ x) {
    int b = blockIdx.y;
    int i = blockIdx.x * blockDim.x + threadIdx.x;   // 0..1023
    float v = x[(size_t)b * IN_F + i];

    float* row = g_A + (size_t)b * KTOT;
    float s = v / (1.0f + expf(-v));                 // SiLU
    row[i] = tf32_rna(s);

    float xc = fminf(fmaxf(v, -1.0f), 1.0f);
    const float g[12] = {-2.2f, -1.8f, -1.4f, -1.0f, -0.6f, -0.2f,
                          0.2f,  0.6f,  1.0f,  1.4f,  1.8f,  2.2f};
    float bas[11];
#pragma unroll
    for (int j = 0; j < 11; j++)
        bas[j] = (xc >= g[j] && xc < g[j + 1]) ? 1.0f : 0.0f;   // half-open, x==1 -> seg 8
#pragma unroll
    for (int k = 1; k <= 3; k++) {
#pragma unroll
        for (int j = 0; j <= 10 - k; j++) {
            float l = (xc - g[j]) / (g[j + k] - g[j]) * bas[j];
            float r = (g[j + k + 1] - xc) / (g[j + k + 1] - g[j + 1]) * bas[j + 1];
            bas[j] = l + r;
        }
    }
    float* dst = row + IN_F + (size_t)i * NB;
#pragma unroll
    for (int j = 0; j < NB; j++) dst[j] = tf32_rna(bas[j]);
}

// =====================================================================
// P1: W = [ tf32(base_weight) | tf32(spline_weight) ]  (O, 9216)
// =====================================================================
__global__ void prep_W_kernel(const float* __restrict__ bw, const float* __restrict__ sw) {
    int o = blockIdx.y;
    int k = blockIdx.x * blockDim.x + threadIdx.x;   // 0..9215
    float v = (k < IN_F) ? bw[(size_t)o * IN_F + k]
                         : sw[(size_t)o * (IN_F * NB) + (k - IN_F)];
    g_W[(size_t)o * KTOT + k] = tf32_rna(v);
}

// =====================================================================
// GEMM: out[m,n] = sum_k A[m,k] * W[n,k]
// tf32 mma.sync m16n8k8, BM=128 x BN=256, 8 warps (2x4), warp tile 64x64,
// 4-stage cp.async pipeline, SW128-swizzled K-major smem tiles, ldmatrix feed.
// =====================================================================
__global__ __launch_bounds__(256, 1)
void kan_gemm_kernel(float* __restrict__ out) {
    extern __shared__ char smem[];
    uint32_t sb = smem_u32(smem);
    int tid = threadIdx.x;
    int wid = tid >> 5;
    int lid = tid & 31;
    int n0 = blockIdx.x * BN;
    int m0 = blockIdx.y * BM;

    // ---- producer addressing: 12 x 16B chunks / thread / stage ----
    // chunk grid: rows = tid>>3 (+32 per u-step), 16B col = tid&7
    int rb = tid >> 3, cb = tid & 7;
    size_t aoff = (size_t)(m0 + rb) * KTOT + cb * 4;     // elements
    size_t boff = (size_t)(n0 + rb) * KTOT + cb * 4;
    uint32_t s0 = SWZ((uint32_t)(rb * 128 + cb * 16));   // +4096 per 32 rows (swizzle-safe)

    auto load_stage = [&](int L) {
        uint32_t base = sb + (uint32_t)(L & (STAGES - 1)) * STAGE_BYTES;
        size_t kb = (size_t)L * BK;
#pragma unroll
        for (int u = 0; u < 4; u++)                      // A: 128 rows x 8 chunks
            cp16(base + s0 + u * 4096, g_A + aoff + (size_t)u * 32 * KTOT + kb);
#pragma unroll
        for (int u = 0; u < 8; u++)                      // B: 256 rows x 8 chunks
            cp16(base + BB_OFF + s0 + u * 4096, g_W + boff + (size_t)u * 32 * KTOT + kb);
    };

    // ---- consumer addressing ----
    int wm = (wid >> 2) * 64;                            // warp m offset in tile
    int wn = (wid & 3) * 64;                             // warp n offset in tile
    // A ldmatrix.x4: mats {rows 0-7 kg0, rows 8-15 kg0, rows 0-7 kg16, rows 8-15 kg16}
    int arow = ((lid & 8) ? 8 : 0) + (lid & 7);
    int akg  = (lid & 16) ? 16 : 0;
    // B ldmatrix.x4: mats {n 0-7 kg0, n 0-7 kg16, n 8-15 kg0, n 8-15 kg16}
    int brow = ((lid & 16) ? 8 : 0) + (lid & 7);
    int bkg  = (lid & 8) ? 16 : 0;

    float acc[4][8][4];
#pragma unroll
    for (int mi = 0; mi < 4; mi++)
#pragma unroll
        for (int ni = 0; ni < 8; ni++)
#pragma unroll
            for (int v = 0; v < 4; v++) acc[mi][ni][v] = 0.0f;

    // ---- pipeline ----
    load_stage(0); CP_COMMIT();
    load_stage(1); CP_COMMIT();
    load_stage(2); CP_COMMIT();

    for (int i = 0; i < NITER; i++) {
        CP_WAIT_2();                 // stage i resident (for this thread's copies)
        __syncthreads();             // all threads' copies visible; frees buf (i-1)%4 reads
        if (i + 3 < NITER) load_stage(i + 3);   // overwrites buf (i-1)%4 — safe post-barrier
        CP_COMMIT();                 // uniform group count (may be empty at tail)

        uint32_t stg = sb + (uint32_t)(i & 3) * STAGE_BYTES;
#pragma unroll
        for (int s = 0; s < 4; s++) {            // 4 x k8 steps = BK 32
            uint32_t a[4][4], b[4][4];
#pragma unroll
            for (int mi = 0; mi < 4; mi++) {
                uint32_t ad = stg + SWZ((uint32_t)((wm + mi * 16 + arow) * 128 + s * 32 + akg));
                LDSM4(a[mi], ad);
            }
#pragma unroll
            for (int p = 0; p < 4; p++) {        // each covers two n8 tiles
                uint32_t bd = stg + BB_OFF +
                              SWZ((uint32_t)((wn + p * 16 + brow) * 128 + s * 32 + bkg));
                LDSM4(b[p], bd);
            }
#pragma unroll
            for (int mi = 0; mi < 4; mi++)
#pragma unroll
                for (int ni = 0; ni < 8; ni++)
                    mma_tf32(acc[mi][ni], a[mi],
                             b[ni >> 1][(ni & 1) * 2], b[ni >> 1][(ni & 1) * 2 + 1]);
        }
    }

    // ---- epilogue: c frag m16n8 f32: rows {t/4, t/4+8}, cols {2*(t%4), +1} ----
    int er = m0 + wm + (lid >> 2);
    int ec = n0 + wn + (lid & 3) * 2;
#pragma unroll
    for (int mi = 0; mi < 4; mi++) {
#pragma unroll
        for (int ni = 0; ni < 8; ni++) {
            float2 v0 = make_float2(acc[mi][ni][0], acc[mi][ni][1]);
            float2 v1 = make_float2(acc[mi][ni][2], acc[mi][ni][3]);
            *(float2*)(out + (size_t)(er + mi * 16) * OUT_F + ec + ni * 8) = v0;
            *(float2*)(out + (size_t)(er + mi * 16 + 8) * OUT_F + ec + ni * 8) = v1;
        }
    }
}

// =====================================================================
extern "C" void kernel_launch(void* const* d_in, const int* in_sizes, int n_in,
                              void* d_out, int out_size) {
    const float* x  = (const float*)d_in[0];   // (8192, 1024)
    const float* bw = (const float*)d_in[1];   // (1024, 1024)
    const float* sw = (const float*)d_in[2];   // (1024, 1024, 8)
    float* out = (float*)d_out;                // (8192, 1024)

    prep_A_kernel<<<dim3(IN_F / 256, BATCH), 256>>>(x);
    prep_W_kernel<<<dim3(KTOT / 256, OUT_F), 256>>>(bw, sw);

    cudaFuncSetAttribute(kan_gemm_kernel, cudaFuncAttributeMaxDynamicSharedMemorySize, SMEM_DYN);
    kan_gemm_kernel<<<dim3(OUT_F / BN, BATCH / BM), 256, SMEM_DYN>>>(out);
}

// round 8
// speedup vs baseline: 2.1842x; 2.1842x over previous
#include <cuda_runtime.h>
#include <cuda_fp16.h>
#include <cstdint>
#include <math.h>

// ---------------- problem constants ----------------
#define BATCH 8192
#define IN_F  1024
#define OUT_F 1024
#define NB    8
#define KTOT  9216                       // 1024 (silu) + 8192 (basis)

// ---------------- GEMM tiling (fp16 HMMA m16n8k16) ----------------
#define BM 128
#define BN 256
#define BK 64                            // 64 halfs = 128 bytes = one SW128 row
#define STAGES 4
#define NITER (KTOT / BK)                // 144
#define STAGE_BYTES ((BM + BN) * 128)    // 49152
#define BB_OFF (BM * 128)                // 16384
#define SMEM_DYN (STAGES * STAGE_BYTES)  // 196608

// scratch (allocation-free rule: __device__ globals)
__device__ __half g_A[(size_t)BATCH * KTOT];   // 151 MB
__device__ __half g_W[(size_t)OUT_F * KTOT];   //  19 MB

// ---------------- helpers ----------------
__device__ __forceinline__ uint32_t smem_u32(const void* p) {
    uint32_t a;
    asm("{ .reg .u64 t; cvta.to.shared.u64 t, %1; cvt.u32.u64 %0, t; }" : "=r"(a) : "l"(p));
    return a;
}

#define SWZ(o) ((o) ^ (((o) >> 3) & 0x70))

__device__ __forceinline__ void cp16(uint32_t dst, const void* src) {
    asm volatile("cp.async.cg.shared.global [%0], [%1], 16;"
                 :: "r"(dst), "l"(__cvta_generic_to_global(src)));
}
#define CP_COMMIT() asm volatile("cp.async.commit_group;" ::: "memory")
#define CP_WAIT_2() asm volatile("cp.async.wait_group 2;" ::: "memory")

#define LDSM4(r, addr) \
    asm volatile("ldmatrix.sync.aligned.m8n8.x4.shared.b16 {%0,%1,%2,%3}, [%4];" \
        : "=r"((r)[0]), "=r"((r)[1]), "=r"((r)[2]), "=r"((r)[3]) : "r"(addr))

// m16n8k16 fp16 MMA, fp32 accumulate (sm_80+ baseline — legal on plain sm_103)
__device__ __forceinline__ void mma_f16(float* c, const uint32_t* a,
                                        uint32_t b0, uint32_t b1) {
    asm volatile(
        "mma.sync.aligned.m16n8k16.row.col.f32.f16.f16.f32 "
        "{%0,%1,%2,%3}, {%4,%5,%6,%7}, {%8,%9}, {%0,%1,%2,%3};"
        : "+f"(c[0]), "+f"(c[1]), "+f"(c[2]), "+f"(c[3])
        : "r"(a[0]), "r"(a[1]), "r"(a[2]), "r"(a[3]), "r"(b0), "r"(b1));
}

// =====================================================================
// P0: A = [ h(silu(x)) | h(cubic B-spline basis(clip(x))) ]  (B, 9216)
// Closed-form uniform cubic B-spline: for zero-order segment seg (0..5),
// nonzero bases are seg..seg+3 with weights
//   {(1-t)^3, 3t^3-6t^2+4, -3t^3+3t^2+3t+1, t^3} / 6,  t = (xc - g_seg)*2.5.
// Matches the reference's half-open-interval semantics: xc==1 -> seg=5, t=0,
// w3=0 (basis index 8 does not exist; guarded).
// =====================================================================
__global__ void prep_A_kernel(const float* __restrict__ x) {
    int b = blockIdx.y;
    int i = blockIdx.x * blockDim.x + threadIdx.x;   // 0..1023
    float v = x[(size_t)b * IN_F + i];

    __half* row = g_A + (size_t)b * KTOT;
    float s = v / (1.0f + expf(-v));                 // SiLU
    row[i] = __float2half_rn(s);

    float xc = fminf(fmaxf(v, -1.0f), 1.0f);
    int seg = (int)floorf((xc + 1.0f) * 2.5f);
    seg = min(max(seg, 0), 5);
    float t = (xc - (-1.0f + 0.4f * (float)seg)) * 2.5f;
    float t2 = t * t, t3 = t2 * t;
    float omt = 1.0f - t;
    const float c6 = 1.0f / 6.0f;
    float w0 = omt * omt * omt * c6;
    float w1 = (3.0f * t3 - 6.0f * t2 + 4.0f) * c6;
    float w2 = (-3.0f * t3 + 3.0f * t2 + 3.0f * t + 1.0f) * c6;
    float w3 = t3 * c6;

    __half h[8];
#pragma unroll
    for (int j = 0; j < 8; j++) h[j] = __float2half_rn(0.0f);
    h[seg] = __float2half_rn(w0);
    h[seg + 1] = __float2half_rn(w1);
    h[seg + 2] = __float2half_rn(w2);
    if (seg + 3 < 8) h[seg + 3] = __float2half_rn(w3);   // seg=5 -> t=0 -> w3=0

    // 8 halfs = 16B, dst 16B-aligned (1024 + 8i halfs)
    *(uint4*)(row + IN_F + (size_t)i * NB) = *(const uint4*)h;
}

// =====================================================================
// P1: W = [ h(base_weight) | h(spline_weight) ]  (O, 9216), 8 elems/thread
// =====================================================================
__global__ void prep_W_kernel(const float* __restrict__ bw, const float* __restrict__ sw) {
    int o = blockIdx.y;
    int k8 = (blockIdx.x * blockDim.x + threadIdx.x) * 8;   // 0..9208, blocks of 8
    const float* src = (k8 < IN_F) ? (bw + (size_t)o * IN_F + k8)
                                   : (sw + (size_t)o * (IN_F * NB) + (k8 - IN_F));
    float4 f0 = *(const float4*)(src);
    float4 f1 = *(const float4*)(src + 4);
    __half h[8];
    h[0] = __float2half_rn(f0.x); h[1] = __float2half_rn(f0.y);
    h[2] = __float2half_rn(f0.z); h[3] = __float2half_rn(f0.w);
    h[4] = __float2half_rn(f1.x); h[5] = __float2half_rn(f1.y);
    h[6] = __float2half_rn(f1.z); h[7] = __float2half_rn(f1.w);
    *(uint4*)(g_W + (size_t)o * KTOT + k8) = *(const uint4*)h;
}

// =====================================================================
// GEMM: out[m,n] = sum_k A[m,k] * W[n,k]
// fp16 mma.sync m16n8k16, BM=128 x BN=256, 8 warps (2x4), warp tile 64x64,
// 4-stage cp.async pipeline, SW128-swizzled K-major smem tiles, ldmatrix feed.
// =====================================================================
__global__ __launch_bounds__(256, 1)
void kan_gemm_kernel(float* __restrict__ out) {
    extern __shared__ char smem[];
    uint32_t sb = smem_u32(smem);
    int tid = threadIdx.x;
    int wid = tid >> 5;
    int lid = tid & 31;
    int n0 = blockIdx.x * BN;
    int m0 = blockIdx.y * BM;

    // ---- producer addressing: 12 x 16B chunks / thread / stage ----
    // chunk grid: rows = tid>>3 (+32 per u-step), 16B col = tid&7
    int rb = tid >> 3, cb = tid & 7;
    size_t aoff = (size_t)(m0 + rb) * KTOT + cb * 8;     // halfs (16B = 8 halfs)
    size_t boff = (size_t)(n0 + rb) * KTOT + cb * 8;
    uint32_t s0 = SWZ((uint32_t)(rb * 128 + cb * 16));   // +4096 per 32 rows (swizzle-safe)

    auto load_stage = [&](int L) {
        uint32_t base = sb + (uint32_t)(L & (STAGES - 1)) * STAGE_BYTES;
        size_t kb = (size_t)L * BK;                      // half-element offset along K
#pragma unroll
        for (int u = 0; u < 4; u++)                      // A: 128 rows x 8 chunks
            cp16(base + s0 + u * 4096, g_A + aoff + (size_t)u * 32 * KTOT + kb);
#pragma unroll
        for (int u = 0; u < 8; u++)                      // B: 256 rows x 8 chunks
            cp16(base + BB_OFF + s0 + u * 4096, g_W + boff + (size_t)u * 32 * KTOT + kb);
    };

    // ---- consumer addressing ----
    int wm = (wid >> 2) * 64;                            // warp m offset in tile
    int wn = (wid & 3) * 64;                             // warp n offset in tile
    // A ldmatrix.x4 mats: {rows0-7 k0-7, rows8-15 k0-7, rows0-7 k8-15, rows8-15 k8-15}
    int arow = ((lid & 8) ? 8 : 0) + (lid & 7);
    int akg  = (lid & 16) ? 16 : 0;                      // byte offset (16B = 8 halfs)
    // B ldmatrix.x4 mats: {n0-7 k0-7, n0-7 k8-15, n8-15 k0-7, n8-15 k8-15}
    int brow = ((lid & 16) ? 8 : 0) + (lid & 7);
    int bkg  = (lid & 8) ? 16 : 0;

    float acc[4][8][4];
#pragma unroll
    for (int mi = 0; mi < 4; mi++)
#pragma unroll
        for (int ni = 0; ni < 8; ni++)
#pragma unroll
            for (int v = 0; v < 4; v++) acc[mi][ni][v] = 0.0f;

    // ---- pipeline ----
    load_stage(0); CP_COMMIT();
    load_stage(1); CP_COMMIT();
    load_stage(2); CP_COMMIT();

    for (int i = 0; i < NITER; i++) {
        CP_WAIT_2();                 // stage i resident (this thread's copies)
        __syncthreads();             // all copies visible; all warps done reading buf (i-1)%4
        if (i + 3 < NITER) load_stage(i + 3);   // overwrites buf (i-1)%4 — safe post-barrier
        CP_COMMIT();                 // uniform group count (may be empty at tail)

        uint32_t stg = sb + (uint32_t)(i & 3) * STAGE_BYTES;
#pragma unroll
        for (int s = 0; s < 4; s++) {            // 4 x k16 steps = BK 64 (32B per step)
            uint32_t a[4][4], b[4][4];
#pragma unroll
            for (int mi = 0; mi < 4; mi++) {
                uint32_t ad = stg + SWZ((uint32_t)((wm + mi * 16 + arow) * 128 + s * 32 + akg));
                LDSM4(a[mi], ad);
            }
#pragma unroll
            for (int p = 0; p < 4; p++) {        // each covers two n8 tiles
                uint32_t bd = stg + BB_OFF +
                              SWZ((uint32_t)((wn + p * 16 + brow) * 128 + s * 32 + bkg));
                LDSM4(b[p], bd);
            }
#pragma unroll
            for (int mi = 0; mi < 4; mi++)
#pragma unroll
                for (int ni = 0; ni < 8; ni++)
                    mma_f16(acc[mi][ni], a[mi],
                            b[ni >> 1][(ni & 1) * 2], b[ni >> 1][(ni & 1) * 2 + 1]);
        }
    }

    // ---- epilogue: c frag m16n8 f32: rows {t/4, t/4+8}, cols {2*(t%4), +1} ----
    int er = m0 + wm + (lid >> 2);
    int ec = n0 + wn + (lid & 3) * 2;
#pragma unroll
    for (int mi = 0; mi < 4; mi++) {
#pragma unroll
        for (int ni = 0; ni < 8; ni++) {
            float2 v0 = make_float2(acc[mi][ni][0], acc[mi][ni][1]);
            float2 v1 = make_float2(acc[mi][ni][2], acc[mi][ni][3]);
            *(float2*)(out + (size_t)(er + mi * 16) * OUT_F + ec + ni * 8) = v0;
            *(float2*)(out + (size_t)(er + mi * 16 + 8) * OUT_F + ec + ni * 8) = v1;
        }
    }
}

// =====================================================================
extern "C" void kernel_launch(void* const* d_in, const int* in_sizes, int n_in,
                              void* d_out, int out_size) {
    const float* x  = (const float*)d_in[0];   // (8192, 1024)
    const float* bw = (const float*)d_in[1];   // (1024, 1024)
    const float* sw = (const float*)d_in[2];   // (1024, 1024, 8)
    float* out = (float*)d_out;                // (8192, 1024)

    prep_A_kernel<<<dim3(IN_F / 256, BATCH), 256>>>(x);
    prep_W_kernel<<<dim3(KTOT / 8 / 128, OUT_F), 128>>>(bw, sw);

    cudaFuncSetAttribute(kan_gemm_kernel, cudaFuncAttributeMaxDynamicSharedMemorySize, SMEM_DYN);
    kan_gemm_kernel<<<dim3(OUT_F / BN, BATCH / BM), 256, SMEM_DYN>>>(out);
}